// round 17
// baseline (speedup 1.0000x reference)
#include <cuda_runtime.h>

// SNN: T=512, B=64, I=1024, H=4096, O=1024, alpha=beta=0.9, thresh=1.0
// Bit-exact reference arithmetic (proven R13-R16):
//   GEMM2: splitK=2 (512-chunks), ascending fp32 FMA chain, combine ascending
//   GEMM3: splitK=8 (512-chunks), same
// R17: 2 phases/step. GEMM2 full-k per CTA (two sequential 512 chains,
//      in-register combine) + fused layer-2 neuron -> p2 eliminated.
//      Duplicated weights in smem -> fewer inst/k (latency headroom).
#define Tn 512
#define Bn 64
#define In 1024
#define Hn 4096
#define On 1024

#define NCTA 128
#define NTHR 256
#define NTOT (NCTA * NTHR)

#define KBLK 32

typedef unsigned long long ull;

// ---------------- persistent device state ----------------
__device__ float g_xt[Tn * In * Bn];          // x transposed: [t][i][b]
__device__ float g_s1[In * Bn], g_m1[In * Bn], g_spk1[In * Bn];   // [i][b]
__device__ float g_s2[Hn * Bn], g_m2[Hn * Bn], g_spk2[Hn * Bn];   // [h][b]
__device__ float g_s3[On * Bn], g_m3[On * Bn];                    // [o][b]
__device__ float g_w1t[In * Hn];              // w1 transposed: [k][h]
__device__ float g_w2t[Hn * On];              // w2 transposed: [k][o]
__device__ float g_p3[8][On * Bn];            // GEMM3 chunk partials [o][b]
__device__ unsigned g_cnt, g_gen;

// ---------------- grid-wide barrier (proven) ----------------
__device__ __forceinline__ void gridbar() {
    __syncthreads();
    if (threadIdx.x == 0) {
        __threadfence();
        unsigned gen = *(volatile unsigned*)&g_gen;
        if (atomicAdd(&g_cnt, 1u) == (unsigned)(NCTA - 1)) {
            g_cnt = 0;
            __threadfence();
            atomicAdd(&g_gen, 1u);
        } else {
            while (*(volatile unsigned*)&g_gen == gen) { __nanosleep(64); }
        }
        __threadfence();
    }
    __syncthreads();
}

// packed f32x2 FMA: two independent fp32 FMAs, bit-identical to scalar FFMA
#define FMA2(d, a, b) asm("fma.rn.f32x2 %0, %1, %2, %0;" : "+l"(d) : "l"(a), "l"(b))

__device__ __forceinline__ float neuron_step(float* __restrict__ S,
                                             float* __restrict__ M,
                                             size_t idx, float inp) {
    float s = S[idx], m = M[idx];
    float r = (m > 1.0f) ? 1.0f : 0.0f;
    s = __fmaf_rn(0.9f, s, inp);
    m = __fsub_rn(__fmaf_rn(0.9f, m, s), r);
    S[idx] = s; M[idx] = m;
    return (m > 1.0f) ? 1.0f : 0.0f;
}

// store a float4 as two duplicated f32x2 pairs (8 floats)
__device__ __forceinline__ void store_dup(float* dst, float4 v) {
    float4 d0; d0.x = v.x; d0.y = v.x; d0.z = v.y; d0.w = v.y;
    float4 d1; d1.x = v.z; d1.y = v.z; d1.z = v.w; d1.w = v.w;
    *(float4*)(dst)     = d0;
    *(float4*)(dst + 4) = d1;
}

// ---------------- GEMM2 one 512-k pass (tile 32h x 64b) ----------------
// acc[j][i]: j = n-pair lane-dup index (2 n), i = b-pair (2x2 b). Ascending k.
// Inner loop: 4 FMA2 + 2 LDS per k per thread-warp.
__device__ __forceinline__ void g2_pass(ull acc[2][2], int n0, int k0,
                                        float* __restrict__ w_s,
                                        float* __restrict__ s_s) {
    const int tid = threadIdx.x;
    const int np  = tid & 15;          // n-pair: n = n0 + np*2 (+0,+1)
    const int bq  = tid >> 4;          // b-quad: b = bq*4 .. +3
    const int wr  = tid >> 3, wc = tid & 7;    // w staging: 32 rows x 8 float4
    const int sr  = tid >> 4, sc = tid & 15;   // s staging: 16(+16) rows x 16 float4

    float4 wv, sv0, sv1;
    wv  = *(const float4*)(g_w1t + (size_t)(k0 + wr) * Hn + n0 + wc * 4);
    sv0 = __ldcv((const float4*)(g_spk1 + (size_t)(k0 + sr) * Bn + sc * 4));
    sv1 = __ldcv((const float4*)(g_spk1 + (size_t)(k0 + sr + 16) * Bn + sc * 4));
    store_dup(w_s + wr * 64 + wc * 8, wv);
    *(float4*)(s_s + sr * 64 + sc * 4) = sv0;
    *(float4*)(s_s + (sr + 16) * 64 + sc * 4) = sv1;
    __syncthreads();

    int buf = 0;
#pragma unroll 1
    for (int blk = 0; blk < 512 / KBLK; blk++) {
        const bool more = (blk + 1 < 512 / KBLK);
        if (more) {
            const int kb = k0 + (blk + 1) * KBLK;
            wv  = *(const float4*)(g_w1t + (size_t)(kb + wr) * Hn + n0 + wc * 4);
            sv0 = __ldcv((const float4*)(g_spk1 + (size_t)(kb + sr) * Bn + sc * 4));
            sv1 = __ldcv((const float4*)(g_spk1 + (size_t)(kb + sr + 16) * Bn + sc * 4));
        }
        const float* wb = w_s + buf * (KBLK * 64);
        const float* sb = s_s + buf * (KBLK * 64);
#pragma unroll
        for (int kk = 0; kk < KBLK; kk++) {
            ulonglong2 w2 = *(const ulonglong2*)(wb + kk * 64 + np * 4);
            ulonglong2 sp = *(const ulonglong2*)(sb + kk * 64 + bq * 4);
            FMA2(acc[0][0], sp.x, w2.x); FMA2(acc[0][1], sp.y, w2.x);
            FMA2(acc[1][0], sp.x, w2.y); FMA2(acc[1][1], sp.y, w2.y);
        }
        if (more) {
            const int nb = buf ^ 1;
            store_dup(w_s + nb * (KBLK * 64) + wr * 64 + wc * 8, wv);
            *(float4*)(s_s + nb * (KBLK * 64) + sr * 64 + sc * 4) = sv0;
            *(float4*)(s_s + nb * (KBLK * 64) + (sr + 16) * 64 + sc * 4) = sv1;
        }
        __syncthreads();
        buf ^= 1;
    }
}

// GEMM2 full-k (2 chained passes) + fused layer-2 neuron
__device__ __forceinline__ void g2_fused(float* __restrict__ w_s,
                                         float* __restrict__ s_s) {
    const int n0 = blockIdx.x * 32;
    const int np = threadIdx.x & 15;
    const int bq = threadIdx.x >> 4;

    ull accA[2][2] = {{0ull, 0ull}, {0ull, 0ull}};
    ull accB[2][2] = {{0ull, 0ull}, {0ull, 0ull}};
    g2_pass(accA, n0, 0, w_s, s_s);
    g2_pass(accB, n0, 512, w_s, s_s);

#pragma unroll
    for (int j = 0; j < 2; j++)
#pragma unroll
        for (int i = 0; i < 2; i++) {
            float2 a = *(float2*)&accA[j][i];
            float2 b = *(float2*)&accB[j][i];
            float cx = __fadd_rn(a.x, b.x);     // splitK=2 combine, in order
            float cy = __fadd_rn(a.y, b.y);
            size_t idx = (size_t)(n0 + np * 2 + j) * Bn + bq * 4 + i * 2;
            g_spk2[idx]     = neuron_step(g_s2, g_m2, idx, cx);
            g_spk2[idx + 1] = neuron_step(g_s2, g_m2, idx + 1, cy);
        }
}

// ---------------- GEMM3 one 512-k chunk (tile 64o x 64b) ----------------
// Thread = 4n x 4b. Inner loop: 8 FMA2 + 3 LDS per k.
__device__ __forceinline__ void g3_chunk(float* __restrict__ w_s,
                                         float* __restrict__ s_s) {
    const int chunk = blockIdx.x >> 4;
    const int n0 = (blockIdx.x & 15) * 64;
    const int k0 = chunk * 512;
    float* __restrict__ part = g_p3[chunk];

    const int tid  = threadIdx.x;
    const int lane = tid & 31, wid = tid >> 5;
    const int nh = (wid & 1) * 32 + (lane & 7) * 4;   // local n (0..63, x4)
    const int bl = (wid >> 1) * 16 + (lane >> 3) * 4; // local b (0..63, x4)
    const int wr = tid >> 3, wc = tid & 7;            // w: 32 rows x (2x 8 float4)
    const int sr = tid >> 4, sc = tid & 15;           // s: 16(+16) rows x 16 float4

    ull acc[4][2];
#pragma unroll
    for (int j = 0; j < 4; j++) { acc[j][0] = 0ull; acc[j][1] = 0ull; }

    float4 wv0, wv1, sv0, sv1;
    wv0 = *(const float4*)(g_w2t + (size_t)(k0 + wr) * On + n0 + wc * 4);
    wv1 = *(const float4*)(g_w2t + (size_t)(k0 + wr) * On + n0 + 32 + wc * 4);
    sv0 = __ldcv((const float4*)(g_spk2 + (size_t)(k0 + sr) * Bn + sc * 4));
    sv1 = __ldcv((const float4*)(g_spk2 + (size_t)(k0 + sr + 16) * Bn + sc * 4));
    store_dup(w_s + wr * 128 + wc * 8, wv0);
    store_dup(w_s + wr * 128 + 64 + wc * 8, wv1);
    *(float4*)(s_s + sr * 64 + sc * 4) = sv0;
    *(float4*)(s_s + (sr + 16) * 64 + sc * 4) = sv1;
    __syncthreads();

    int buf = 0;
#pragma unroll 1
    for (int blk = 0; blk < 512 / KBLK; blk++) {
        const bool more = (blk + 1 < 512 / KBLK);
        if (more) {
            const int kb = k0 + (blk + 1) * KBLK;
            wv0 = *(const float4*)(g_w2t + (size_t)(kb + wr) * On + n0 + wc * 4);
            wv1 = *(const float4*)(g_w2t + (size_t)(kb + wr) * On + n0 + 32 + wc * 4);
            sv0 = __ldcv((const float4*)(g_spk2 + (size_t)(kb + sr) * Bn + sc * 4));
            sv1 = __ldcv((const float4*)(g_spk2 + (size_t)(kb + sr + 16) * Bn + sc * 4));
        }
        const float* wb = w_s + buf * (KBLK * 128);
        const float* sb = s_s + buf * (KBLK * 64);
#pragma unroll
        for (int kk = 0; kk < KBLK; kk++) {
            ulonglong2 wA = *(const ulonglong2*)(wb + kk * 128 + nh * 2);
            ulonglong2 wB = *(const ulonglong2*)(wb + kk * 128 + nh * 2 + 4);
            ulonglong2 sp = *(const ulonglong2*)(sb + kk * 64 + bl);
            FMA2(acc[0][0], sp.x, wA.x); FMA2(acc[0][1], sp.y, wA.x);
            FMA2(acc[1][0], sp.x, wA.y); FMA2(acc[1][1], sp.y, wA.y);
            FMA2(acc[2][0], sp.x, wB.x); FMA2(acc[2][1], sp.y, wB.x);
            FMA2(acc[3][0], sp.x, wB.y); FMA2(acc[3][1], sp.y, wB.y);
        }
        if (more) {
            const int nb = buf ^ 1;
            store_dup(w_s + nb * (KBLK * 128) + wr * 128 + wc * 8, wv0);
            store_dup(w_s + nb * (KBLK * 128) + wr * 128 + 64 + wc * 8, wv1);
            *(float4*)(s_s + nb * (KBLK * 64) + sr * 64 + sc * 4) = sv0;
            *(float4*)(s_s + nb * (KBLK * 64) + (sr + 16) * 64 + sc * 4) = sv1;
        }
        __syncthreads();
        buf ^= 1;
    }
#pragma unroll
    for (int j = 0; j < 4; j++) {
        float2 a = *(float2*)&acc[j][0];
        float2 b = *(float2*)&acc[j][1];
        float4 o; o.x = a.x; o.y = a.y; o.z = b.x; o.w = b.y;
        *(float4*)(part + (size_t)(n0 + nh + j) * Bn + bl) = o;
    }
}

// ---------------- elementwise phases ----------------
__device__ __forceinline__ void phaseA(int t, int gt) {
    const float* xt = g_xt + (size_t)t * In * Bn;
    for (int i = gt; i < In * Bn; i += NTOT)
        g_spk1[i] = neuron_step(g_s1, g_m1, i, xt[i]);
}

__device__ __forceinline__ void phaseL3(float* __restrict__ out, int t, int gt) {
    float* ot = out + (size_t)t * Bn * On;
    for (int i = gt; i < On * Bn; i += NTOT) {
        float cur = __ldcv(&g_p3[0][i]);
#pragma unroll
        for (int c = 1; c < 8; c++) cur = __fadd_rn(cur, __ldcv(&g_p3[c][i]));
        float spk = neuron_step(g_s3, g_m3, i, cur);
        int o = i >> 6, b = i & 63;
        ot[(size_t)b * On + o] = spk;    // out stays [t][b][o]
    }
}

// ---------------- persistent kernel ----------------
__global__ void __launch_bounds__(NTHR, 1)
snn_kernel(const float* __restrict__ x, const float* __restrict__ w1,
           const float* __restrict__ w2, float* __restrict__ out) {
    __shared__ float pool[12288];   // 48KB: G3 = 2*(32*128 + 32*64); G2 fits inside
    const int gt = blockIdx.x * NTHR + threadIdx.x;

    // init: zero neuron state; transpose weights + x (exact fp32 copies)
    for (int i = gt; i < In * Bn; i += NTOT) { g_s1[i] = 0.0f; g_m1[i] = 0.0f; }
    for (int i = gt; i < Hn * Bn; i += NTOT) { g_s2[i] = 0.0f; g_m2[i] = 0.0f; }
    for (int i = gt; i < On * Bn; i += NTOT) { g_s3[i] = 0.0f; g_m3[i] = 0.0f; }
    for (int e = gt; e < In * Hn; e += NTOT) {
        int k = e >> 12, h = e & (Hn - 1);
        g_w1t[e] = w1[(size_t)h * In + k];
    }
    for (int e = gt; e < Hn * On; e += NTOT) {
        int k = e >> 10, o = e & (On - 1);
        g_w2t[e] = w2[(size_t)o * Hn + k];
    }
    for (size_t e = gt; e < (size_t)Tn * In * Bn; e += NTOT) {
        size_t t = e >> 16;                 // In*Bn = 65536
        int r = (int)(e & 65535);
        int i = r >> 6, b = r & 63;
        g_xt[e] = x[(t << 16) + (size_t)b * In + i];
    }
    gridbar();

    phaseA(0, gt);
    gridbar();

    // G2 smem carve: w = pool[buf*2048*2? -> w_s at pool, s_s at pool+4096]
    // G2 per buf: w 32*64=2048, s 32*64=2048 -> w: pool[0..4096), s: pool[4096..8192)
    // G3 per buf: w 32*128=4096 -> w: pool[0..8192), s: pool[8192..12288)
    for (int t = 0; t < Tn; t++) {
        // P1: GEMM2 full-k + fused layer-2 neurons; layer-3 neurons for t-1
        g2_fused(pool, pool + 4096);
        if (t > 0) phaseL3(out, t - 1, gt);
        gridbar();
        // P2: GEMM3 chunk partials; layer-1 neurons for t+1
        g3_chunk(pool, pool + 8192);
        if (t + 1 < Tn) phaseA(t + 1, gt);
        gridbar();
    }
    phaseL3(out, Tn - 1, gt);
}

extern "C" void kernel_launch(void* const* d_in, const int* in_sizes, int n_in,
                              void* d_out, int out_size) {
    const float* x  = (const float*)d_in[0];   // [512,64,1024]
    const float* w1 = (const float*)d_in[1];   // [4096,1024]
    const float* w2 = (const float*)d_in[2];   // [1024,4096]
    float* out = (float*)d_out;                // [512,64,1024]
    snn_kernel<<<NCTA, NTHR>>>(x, w1, w2, out);
}